// round 5
// baseline (speedup 1.0000x reference)
#include <cuda_runtime.h>
#include <math.h>

#define Bq     16
#define Cq     256
#define HWq    16384
#define INTERq 128
#define CHUNK_PX 512
#define CHUNKS  (HWq / CHUNK_PX)   // 32 chunks per sample

// scratch (no atomics anywhere)
__device__ float g_csum[Bq * CHUNKS * Cq];  // [b][chunk][c] partial channel sums (512 KB)
__device__ float g_p   [Bq * Cq];           // pooled means
__device__ float g_wy  [Bq * Cq];           // pre-BN activations
__device__ int   g_idx [Bq * 3];            // top-3 channels per sample

__device__ __forceinline__ float gelu_exact(float v) {
    return 0.5f * v * (1.0f + erff(v * 0.70710678118654752f));
}

__device__ __forceinline__ float warp_sum(float s) {
    s += __shfl_down_sync(0xffffffffu, s, 16);
    s += __shfl_down_sync(0xffffffffu, s, 8);
    s += __shfl_down_sync(0xffffffffu, s, 4);
    s += __shfl_down_sync(0xffffffffu, s, 2);
    s += __shfl_down_sync(0xffffffffu, s, 1);
    return s;
}

// ---------------------------------------------------------------------------
// K1: single streaming pass over x. Block = (b, 512-pixel chunk), 256 threads.
//     Thread owns pixels (chunk*512 + t*2, +1) across ALL 256 channels:
//       - per-pixel W3-dot accumulates in 2 registers (no cross-thread reduce)
//       - per-channel sum: one smem store/channel; block-reduce every 32 ch.
//     Per channel row the block reads 2 KB CONTIGUOUS (DRAM-friendly).
// ---------------------------------------------------------------------------
__global__ __launch_bounds__(256) void k1_stream(const float* __restrict__ x,
                                                 const float* __restrict__ W3,
                                                 float* __restrict__ out) {
    __shared__ float sw[Cq];
    __shared__ float scs[32][256];   // 32 KB: [channel-in-round][thread]
    __shared__ float sred[32][8];

    const int b     = blockIdx.x >> 5;
    const int chunk = blockIdx.x & (CHUNKS - 1);
    const int t = threadIdx.x;

    for (int i = t; i < Cq; i += 256) sw[i] = W3[i];
    __syncthreads();

    const float* xb = x + (size_t)b * Cq * HWq + (size_t)chunk * CHUNK_PX + (size_t)t * 2;

    float2 dot = make_float2(0.f, 0.f);

    for (int cc = 0; cc < Cq; cc += 32) {
        #pragma unroll 8
        for (int j = 0; j < 32; ++j) {
            const int c = cc + j;
            const float2 v = *reinterpret_cast<const float2*>(xb + (size_t)c * HWq);
            const float w = sw[c];
            dot.x = fmaf(v.x, w, dot.x);
            dot.y = fmaf(v.y, w, dot.y);
            scs[j][t] = v.x + v.y;
        }
        __syncthreads();
        // stage 1: 8 threads per channel, 32 adds each
        {
            const int ch = t >> 3, part = t & 7;
            float s = 0.f;
            #pragma unroll
            for (int k = 0; k < 32; ++k) s += scs[ch][part + 8 * k];
            sred[ch][part] = s;
        }
        __syncthreads();
        // stage 2: thread t<32 finalizes channel cc+t
        if (t < 32) {
            float s = 0.f;
            #pragma unroll
            for (int k = 0; k < 8; ++k) s += sred[t][k];
            g_csum[((size_t)b * CHUNKS + chunk) * Cq + cc + t] = s;
        }
        __syncthreads();
    }

    float2 o;
    o.x = gelu_exact(dot.x);
    o.y = gelu_exact(dot.y);
    *reinterpret_cast<float2*>(out + (size_t)b * 4 * HWq
                               + (size_t)chunk * CHUNK_PX + (size_t)t * 2) = o;
}

// ---------------------------------------------------------------------------
// K2: one block per batch sample (16 blocks x 256 threads).
// ---------------------------------------------------------------------------
__device__ __forceinline__ void proj_cols(const float* __restrict__ W,
                                          const float* __restrict__ bias,
                                          const float* sp, float* dst,
                                          int warp, int lane) {
    #pragma unroll 2
    for (int i = 0; i < 16; ++i) {
        const int col = warp * 16 + i;
        float a = 0.f;
        #pragma unroll
        for (int k = 0; k < 8; ++k) {
            const int idx = k * 32 + lane;
            a = fmaf(__ldg(W + col * Cq + idx), sp[idx], a);
        }
        a = warp_sum(a);
        if (lane == 0) dst[col] = a + bias[col];
    }
}

__global__ __launch_bounds__(256) void k2_perbatch(
    const float* __restrict__ Wg, const float* __restrict__ bg,
    const float* __restrict__ Wt, const float* __restrict__ bt,
    const float* __restrict__ Wp, const float* __restrict__ bp,
    const float* __restrict__ Wf, const float* __restrict__ bf,
    const float* __restrict__ Wz, const float* __restrict__ bz)
{
    __shared__ float sp[Cq];
    __shared__ float s_g[INTERq], s_th[INTERq], s_ph[INTERq];
    __shared__ float sf_sh;

    const int b    = blockIdx.x;
    const int t    = threadIdx.x;
    const int lane = t & 31;
    const int warp = t >> 5;

    {
        const float* cs = g_csum + (size_t)b * CHUNKS * Cq + t;
        float s = 0.f;
        #pragma unroll 8
        for (int k = 0; k < CHUNKS; ++k) s += cs[(size_t)k * Cq];
        const float p = s * (1.0f / (float)HWq);
        sp[t] = p;
        g_p[b * Cq + t] = p;
    }
    __syncthreads();

    proj_cols(Wg, bg, sp, s_g,  warp, lane);
    proj_cols(Wt, bt, sp, s_th, warp, lane);
    proj_cols(Wp, bp, sp, s_ph, warp, lane);
    __syncthreads();

    if (warp == 0) {
        float a = 0.f;
        #pragma unroll
        for (int k = 0; k < 8; ++k) {
            const int i = k * 32 + lane;
            const float v = (i < INTERq) ? s_th[i] : s_ph[i - INTERq];
            a = fmaf(v, __ldg(Wf + i), a);
        }
        a = warp_sum(a);
        if (lane == 0) sf_sh = fmaxf(a + bf[0], 0.f);
    }
    __syncthreads();
    const float f = sf_sh;

    #pragma unroll 2
    for (int i = 0; i < 32; ++i) {
        const int col = warp * 32 + i;
        float a = 0.f;
        #pragma unroll
        for (int k = 0; k < 4; ++k) {
            const int idx = k * 32 + lane;
            a = fmaf(__ldg(Wz + col * INTERq + idx), s_g[idx], a);
        }
        a = warp_sum(a);
        if (lane == 0) g_wy[b * Cq + col] = fmaf(f, a, bz[col]);
    }
}

// ---------------------------------------------------------------------------
// K3: single block, 512 threads. BN over batch + residual, warp-per-sample
//     top-3 via shuffle-argmax (ties -> lowest index, matches lax.top_k).
// ---------------------------------------------------------------------------
__global__ __launch_bounds__(512) void k3_bn_topk(const float* __restrict__ gamma,
                                                  const float* __restrict__ beta) {
    __shared__ float sz[Bq * Cq];
    const int t = threadIdx.x;

    if (t < Cq) {
        const int c = t;
        float vals[Bq];
        #pragma unroll
        for (int b = 0; b < Bq; ++b) vals[b] = g_wy[b * Cq + c];
        float m = 0.f;
        #pragma unroll
        for (int b = 0; b < Bq; ++b) m += vals[b];
        m *= (1.0f / (float)Bq);
        float var = 0.f;
        #pragma unroll
        for (int b = 0; b < Bq; ++b) { const float d = vals[b] - m; var = fmaf(d, d, var); }
        var *= (1.0f / (float)Bq);
        const float inv = rsqrtf(var + 1e-5f);
        const float ga = gamma[c], be = beta[c];
        #pragma unroll
        for (int b = 0; b < Bq; ++b)
            sz[b * Cq + c] = fmaf(ga * (vals[b] - m), inv, be) + g_p[b * Cq + c];
    }
    __syncthreads();

    const int warp = t >> 5;   // 16 warps = 16 samples
    const int lane = t & 31;
    {
        float v[8];
        const int base = warp * Cq;
        #pragma unroll
        for (int k = 0; k < 8; ++k) v[k] = sz[base + k * 32 + lane];

        for (int j = 0; j < 3; ++j) {
            float bv = -INFINITY;
            int   bi = 0x7fffffff;
            #pragma unroll
            for (int k = 0; k < 8; ++k) {
                const int idx = k * 32 + lane;
                if (v[k] > bv) { bv = v[k]; bi = idx; }
            }
            #pragma unroll
            for (int off = 16; off > 0; off >>= 1) {
                const float ov = __shfl_down_sync(0xffffffffu, bv, off);
                const int   oi = __shfl_down_sync(0xffffffffu, bi, off);
                if (ov > bv || (ov == bv && oi < bi)) { bv = ov; bi = oi; }
            }
            bi = __shfl_sync(0xffffffffu, bi, 0);
            if (lane == 0) g_idx[warp * 3 + j] = bi;
            const int kk = bi >> 5;
            if ((bi & 31) == lane) {
                #pragma unroll
                for (int k = 0; k < 8; ++k) if (k == kk) v[k] = -INFINITY;
            }
        }
    }
}

// ---------------------------------------------------------------------------
// K4: gather top-3 channels into output channels 1..3.
// ---------------------------------------------------------------------------
__global__ __launch_bounds__(256) void k4_gather(const float* __restrict__ x,
                                                 float* __restrict__ out) {
    const int q    = blockIdx.x >> 4;   // b*3 + j
    const int part = blockIdx.x & 15;
    const int b = q / 3, j = q % 3;
    const int ch = g_idx[b * 3 + j];
    const size_t pos = (size_t)part * 1024 + (size_t)threadIdx.x * 4;
    const float4 v = *reinterpret_cast<const float4*>(
        x + ((size_t)b * Cq + ch) * HWq + pos);
    *reinterpret_cast<float4*>(
        out + ((size_t)b * 4 + 1 + j) * HWq + pos) = v;
}

extern "C" void kernel_launch(void* const* d_in, const int* in_sizes, int n_in,
                              void* d_out, int out_size) {
    const float* x     = (const float*)d_in[0];
    const float* Wg    = (const float*)d_in[1];
    const float* bg    = (const float*)d_in[2];
    const float* Wt    = (const float*)d_in[3];
    const float* bt    = (const float*)d_in[4];
    const float* Wp    = (const float*)d_in[5];
    const float* bp    = (const float*)d_in[6];
    const float* Wf    = (const float*)d_in[7];
    const float* bf    = (const float*)d_in[8];
    const float* Wz    = (const float*)d_in[9];
    const float* bz    = (const float*)d_in[10];
    const float* gamma = (const float*)d_in[11];
    const float* beta  = (const float*)d_in[12];
    const float* W3    = (const float*)d_in[13];
    float* out = (float*)d_out;

    k1_stream<<<Bq * CHUNKS, 256>>>(x, W3, out);
    k2_perbatch<<<Bq, 256>>>(Wg, bg, Wt, bt, Wp, bp, Wf, bf, Wz, bz);
    k3_bn_topk<<<1, 512>>>(gamma, beta);
    k4_gather<<<Bq * 3 * 16, 256>>>(x, out);
}

// round 8
// speedup vs baseline: 1.0142x; 1.0142x over previous
#include <cuda_runtime.h>
#include <cstdint>
#include <math.h>

#define Bq     16
#define Cq     256
#define HWq    16384
#define INTERq 128

// K1 pipeline geometry
#define PX      512                 // pixels per block
#define CHUNKS  (HWq / PX)          // 32 chunks per sample
#define CPS     32                  // channels per stage
#define STAGES  (Cq / CPS)          // 8 stages
#define ROWF    516                 // floats per smem row (512 + 4 pad, 16B-mult)
#define BUFF    (CPS * ROWF)        // 16512 floats per stage buffer
#define SMEMF   (2 * BUFF + Cq + 256)   // bufs + sw3 + sred

// scratch (no atomics anywhere)
__device__ float g_csum[Bq * CHUNKS * Cq];  // [b][chunk][c] partial channel sums (512 KB)
__device__ float g_p   [Bq * Cq];
__device__ float g_wy  [Bq * Cq];
__device__ int   g_idx [Bq * 3];

__device__ __forceinline__ float gelu_exact(float v) {
    return 0.5f * v * (1.0f + erff(v * 0.70710678118654752f));
}

__device__ __forceinline__ float warp_sum(float s) {
    s += __shfl_down_sync(0xffffffffu, s, 16);
    s += __shfl_down_sync(0xffffffffu, s, 8);
    s += __shfl_down_sync(0xffffffffu, s, 4);
    s += __shfl_down_sync(0xffffffffu, s, 2);
    s += __shfl_down_sync(0xffffffffu, s, 1);
    return s;
}

__device__ __forceinline__ void cp_async16(unsigned int smem_addr, const void* gptr) {
    asm volatile("cp.async.cg.shared.global [%0], [%1], 16;\n"
                 :: "r"(smem_addr), "l"(gptr) : "memory");
}
__device__ __forceinline__ void cp_commit() {
    asm volatile("cp.async.commit_group;\n" ::: "memory");
}
template <int N>
__device__ __forceinline__ void cp_wait() {
    asm volatile("cp.async.wait_group %0;\n" :: "n"(N) : "memory");
}

// ---------------------------------------------------------------------------
// K1: cp.async-staged streaming pass over x.
//   grid = 16 x 32 = 512 blocks, 256 threads, ~134 KB dynamic smem.
//   Block owns (b, 512-pixel chunk); loops 8 stages of 32 channels.
//   Async engine fills stage s+1 while SM computes stage s from SMEM.
//   WAIT DISCIPLINE: consuming stage s requires pending groups <= 1
//   (the only allowed in-flight group is stage s+1, in the other buffer).
// ---------------------------------------------------------------------------
__global__ __launch_bounds__(256) void k1_stream(const float* __restrict__ x,
                                                 const float* __restrict__ W3,
                                                 float* __restrict__ out) {
    extern __shared__ float smemf[];
    float* buf[2] = { smemf, smemf + BUFF };
    float* sw     = smemf + 2 * BUFF;        // 256 floats
    float* sred   = sw + Cq;                 // 32 x 8

    const int b     = blockIdx.x >> 5;
    const int chunk = blockIdx.x & (CHUNKS - 1);
    const int t     = threadIdx.x;
    const int ch_own  = t & 31;
    const int slot    = t >> 5;

    for (int i = t; i < Cq; i += 256) sw[i] = W3[i];

    const float* xbase = x + (size_t)b * Cq * HWq + (size_t)chunk * PX;

    // issue one stage: 32 rows x 2048 B = 4096 cp.async of 16 B; 16 per thread
    auto issue_stage = [&](int s) {
        float* dst = buf[s & 1];
        const float* src = xbase + (size_t)(s * CPS) * HWq;
        #pragma unroll
        for (int k = 0; k < 16; ++k) {
            const int idx = t + k * 256;
            const int ch  = idx >> 7;          // 128 x 16B segs per row
            const int seg = idx & 127;
            const unsigned int daddr = (unsigned int)__cvta_generic_to_shared(
                dst + ch * ROWF) + seg * 16;
            cp_async16(daddr, src + (size_t)ch * HWq + seg * 4);
        }
        cp_commit();
    };

    issue_stage(0);
    issue_stage(1);

    float2 dot = make_float2(0.f, 0.f);

    for (int s = 0; s < STAGES; ++s) {
        // stage s must be complete before reading: allow only stage s+1 pending
        if (s + 1 < STAGES) cp_wait<1>(); else cp_wait<0>();
        __syncthreads();

        const float* bf = buf[s & 1];

        // per-pixel dot: thread t = pixel pair t (conflict-free, consecutive)
        #pragma unroll 8
        for (int i = 0; i < CPS; ++i) {
            const float w = sw[s * CPS + i];
            const float2 v = *reinterpret_cast<const float2*>(bf + i * ROWF + 2 * t);
            dot.x = fmaf(v.x, w, dot.x);
            dot.y = fmaf(v.y, w, dot.y);
        }

        // channel sums: staggered sweep (start offset = ch_own) -> conflict-free
        {
            float a = 0.f;
            const float* row = bf + ch_own * ROWF + slot * 64;
            #pragma unroll 8
            for (int i = 0; i < 64; ++i) {
                const int px = (i + ch_own) & 63;
                a += row[px];
            }
            sred[ch_own * 8 + slot] = a;
        }
        __syncthreads();

        // finalize csum (t<32) + refill the buffer we just finished
        if (t < 32) {
            const float* r = sred + t * 8;
            const float ssum = ((r[0] + r[1]) + (r[2] + r[3]))
                             + ((r[4] + r[5]) + (r[6] + r[7]));
            g_csum[((size_t)b * CHUNKS + chunk) * Cq + s * CPS + t] = ssum;
        }
        if (s + 2 < STAGES) issue_stage(s + 2);
    }

    float2 o;
    o.x = gelu_exact(dot.x);
    o.y = gelu_exact(dot.y);
    *reinterpret_cast<float2*>(out + (size_t)b * 4 * HWq
                               + (size_t)chunk * PX + 2 * t) = o;
}

// ---------------------------------------------------------------------------
// K2: one block per batch sample (16 blocks x 256 threads).
// ---------------------------------------------------------------------------
__device__ __forceinline__ void proj_cols(const float* __restrict__ W,
                                          const float* __restrict__ bias,
                                          const float* sp, float* dst,
                                          int warp, int lane) {
    #pragma unroll 2
    for (int i = 0; i < 16; ++i) {
        const int col = warp * 16 + i;
        float a = 0.f;
        #pragma unroll
        for (int k = 0; k < 8; ++k) {
            const int idx = k * 32 + lane;
            a = fmaf(__ldg(W + col * Cq + idx), sp[idx], a);
        }
        a = warp_sum(a);
        if (lane == 0) dst[col] = a + bias[col];
    }
}

__global__ __launch_bounds__(256) void k2_perbatch(
    const float* __restrict__ Wg, const float* __restrict__ bg,
    const float* __restrict__ Wt, const float* __restrict__ bt,
    const float* __restrict__ Wp, const float* __restrict__ bp,
    const float* __restrict__ Wf, const float* __restrict__ bf,
    const float* __restrict__ Wz, const float* __restrict__ bz)
{
    __shared__ float sp[Cq];
    __shared__ float s_g[INTERq], s_th[INTERq], s_ph[INTERq];
    __shared__ float sf_sh;

    const int b    = blockIdx.x;
    const int t    = threadIdx.x;
    const int lane = t & 31;
    const int warp = t >> 5;

    {
        const float* cs = g_csum + (size_t)b * CHUNKS * Cq + t;
        float s = 0.f;
        #pragma unroll 8
        for (int k = 0; k < CHUNKS; ++k) s += cs[(size_t)k * Cq];
        const float p = s * (1.0f / (float)HWq);
        sp[t] = p;
        g_p[b * Cq + t] = p;
    }
    __syncthreads();

    proj_cols(Wg, bg, sp, s_g,  warp, lane);
    proj_cols(Wt, bt, sp, s_th, warp, lane);
    proj_cols(Wp, bp, sp, s_ph, warp, lane);
    __syncthreads();

    if (warp == 0) {
        float a = 0.f;
        #pragma unroll
        for (int k = 0; k < 8; ++k) {
            const int i = k * 32 + lane;
            const float v = (i < INTERq) ? s_th[i] : s_ph[i - INTERq];
            a = fmaf(v, __ldg(Wf + i), a);
        }
        a = warp_sum(a);
        if (lane == 0) sf_sh = fmaxf(a + bf[0], 0.f);
    }
    __syncthreads();
    const float f = sf_sh;

    #pragma unroll 2
    for (int i = 0; i < 32; ++i) {
        const int col = warp * 32 + i;
        float a = 0.f;
        #pragma unroll
        for (int k = 0; k < 4; ++k) {
            const int idx = k * 32 + lane;
            a = fmaf(__ldg(Wz + col * INTERq + idx), s_g[idx], a);
        }
        a = warp_sum(a);
        if (lane == 0) g_wy[b * Cq + col] = fmaf(f, a, bz[col]);
    }
}

// ---------------------------------------------------------------------------
// K3: single block, 512 threads. BN over batch + residual, warp-per-sample
//     top-3 via shuffle-argmax (ties -> lowest index, matches lax.top_k).
// ---------------------------------------------------------------------------
__global__ __launch_bounds__(512) void k3_bn_topk(const float* __restrict__ gamma,
                                                  const float* __restrict__ beta) {
    __shared__ float sz[Bq * Cq];
    const int t = threadIdx.x;

    if (t < Cq) {
        const int c = t;
        float vals[Bq];
        #pragma unroll
        for (int b = 0; b < Bq; ++b) vals[b] = g_wy[b * Cq + c];
        float m = 0.f;
        #pragma unroll
        for (int b = 0; b < Bq; ++b) m += vals[b];
        m *= (1.0f / (float)Bq);
        float var = 0.f;
        #pragma unroll
        for (int b = 0; b < Bq; ++b) { const float d = vals[b] - m; var = fmaf(d, d, var); }
        var *= (1.0f / (float)Bq);
        const float inv = rsqrtf(var + 1e-5f);
        const float ga = gamma[c], be = beta[c];
        #pragma unroll
        for (int b = 0; b < Bq; ++b)
            sz[b * Cq + c] = fmaf(ga * (vals[b] - m), inv, be) + g_p[b * Cq + c];
    }
    __syncthreads();

    const int warp = t >> 5;   // 16 warps = 16 samples
    const int lane = t & 31;
    {
        float v[8];
        const int base = warp * Cq;
        #pragma unroll
        for (int k = 0; k < 8; ++k) v[k] = sz[base + k * 32 + lane];

        for (int j = 0; j < 3; ++j) {
            float bv = -INFINITY;
            int   bi = 0x7fffffff;
            #pragma unroll
            for (int k = 0; k < 8; ++k) {
                const int idx = k * 32 + lane;
                if (v[k] > bv) { bv = v[k]; bi = idx; }
            }
            #pragma unroll
            for (int off = 16; off > 0; off >>= 1) {
                const float ov = __shfl_down_sync(0xffffffffu, bv, off);
                const int   oi = __shfl_down_sync(0xffffffffu, bi, off);
                if (ov > bv || (ov == bv && oi < bi)) { bv = ov; bi = oi; }
            }
            bi = __shfl_sync(0xffffffffu, bi, 0);
            if (lane == 0) g_idx[warp * 3 + j] = bi;
            const int kk = bi >> 5;
            if ((bi & 31) == lane) {
                #pragma unroll
                for (int k = 0; k < 8; ++k) if (k == kk) v[k] = -INFINITY;
            }
        }
    }
}

// ---------------------------------------------------------------------------
// K4: gather top-3 channels into output channels 1..3.
// ---------------------------------------------------------------------------
__global__ __launch_bounds__(256) void k4_gather(const float* __restrict__ x,
                                                 float* __restrict__ out) {
    const int q    = blockIdx.x >> 4;   // b*3 + j
    const int part = blockIdx.x & 15;
    const int b = q / 3, j = q % 3;
    const int ch = g_idx[b * 3 + j];
    const size_t pos = (size_t)part * 1024 + (size_t)threadIdx.x * 4;
    const float4 v = *reinterpret_cast<const float4*>(
        x + ((size_t)b * Cq + ch) * HWq + pos);
    *reinterpret_cast<float4*>(
        out + ((size_t)b * 4 + 1 + j) * HWq + pos) = v;
}

extern "C" void kernel_launch(void* const* d_in, const int* in_sizes, int n_in,
                              void* d_out, int out_size) {
    const float* x     = (const float*)d_in[0];
    const float* Wg    = (const float*)d_in[1];
    const float* bg    = (const float*)d_in[2];
    const float* Wt    = (const float*)d_in[3];
    const float* bt    = (const float*)d_in[4];
    const float* Wp    = (const float*)d_in[5];
    const float* bp    = (const float*)d_in[6];
    const float* Wf    = (const float*)d_in[7];
    const float* bf    = (const float*)d_in[8];
    const float* Wz    = (const float*)d_in[9];
    const float* bz    = (const float*)d_in[10];
    const float* gamma = (const float*)d_in[11];
    const float* beta  = (const float*)d_in[12];
    const float* W3    = (const float*)d_in[13];
    float* out = (float*)d_out;

    const int smem_bytes = SMEMF * 4;   // ~134 KB
    cudaFuncSetAttribute(k1_stream, cudaFuncAttributeMaxDynamicSharedMemorySize,
                         smem_bytes);

    k1_stream<<<Bq * CHUNKS, 256, smem_bytes>>>(x, W3, out);
    k2_perbatch<<<Bq, 256>>>(Wg, bg, Wt, bt, Wp, bp, Wf, bf, Wz, bz);
    k3_bn_topk<<<1, 512>>>(gamma, beta);
    k4_gather<<<Bq * 3 * 16, 256>>>(x, out);
}

// round 9
// speedup vs baseline: 1.0892x; 1.0740x over previous
#include <cuda_runtime.h>
#include <cstdint>
#include <math.h>

#define Bq     16
#define Cq     256
#define HWq    16384
#define INTERq 128
#define GRPS   16            // channel groups
#define CPGR   16            // channels per group
#define QS     4             // pixel quarters
#define PXQ    (HWq / QS)    // 4096 pixels per quarter

// scratch (no atomics anywhere)
__device__ float g_csum[Bq * Cq * QS];          // [b][c][q] channel-sum quarters (64 KB)
__device__ float g_part[Bq * GRPS * HWq];       // [b][g][px] partial dots (16 MB)
__device__ float g_p   [Bq * Cq];
__device__ float g_wy  [Bq * Cq];
__device__ int   g_idx [Bq * 3];

__device__ __forceinline__ float gelu_exact(float v) {
    return 0.5f * v * (1.0f + erff(v * 0.70710678118654752f));
}

__device__ __forceinline__ float warp_sum(float s) {
    s += __shfl_down_sync(0xffffffffu, s, 16);
    s += __shfl_down_sync(0xffffffffu, s, 8);
    s += __shfl_down_sync(0xffffffffu, s, 4);
    s += __shfl_down_sync(0xffffffffu, s, 2);
    s += __shfl_down_sync(0xffffffffu, s, 1);
    return s;
}

// ---------------------------------------------------------------------------
// K1a: LINEAR streaming pass over x.
//   grid = b(16) x group(16) x quarter(4) = 1024 blocks, 256 threads.
//   Block reads 16 channel-runs of 16 KB CONTIGUOUS each (stride 64 KB).
//   Thread owns 16 pixels (4 float4 register accumulators) fixed across the
//   16 channels -> per-pixel dot partial needs NO cross-thread reduction.
//   Channel sums: one warp_sum per channel (2.5 SHFL/KB), smem finalize.
// ---------------------------------------------------------------------------
__global__ __launch_bounds__(256) void k1a_stream(const float* __restrict__ x,
                                                  const float* __restrict__ W3) {
    __shared__ float sw[CPGR];
    __shared__ float scs[CPGR][8];

    const int q = blockIdx.x & 3;
    const int g = (blockIdx.x >> 2) & 15;
    const int b = blockIdx.x >> 6;
    const int t    = threadIdx.x;
    const int lane = t & 31;
    const int warp = t >> 5;

    if (t < CPGR) sw[t] = W3[g * CPGR + t];
    __syncthreads();

    const float* xb = x + ((size_t)b * Cq + (size_t)g * CPGR) * HWq
                        + (size_t)q * PXQ + (size_t)t * 4;

    float4 a0 = make_float4(0.f,0.f,0.f,0.f);
    float4 a1 = a0, a2 = a0, a3 = a0;

    #pragma unroll 4
    for (int c = 0; c < CPGR; ++c) {
        const float* xc = xb + (size_t)c * HWq;
        const float4 v0 = *reinterpret_cast<const float4*>(xc);
        const float4 v1 = *reinterpret_cast<const float4*>(xc + 1024);
        const float4 v2 = *reinterpret_cast<const float4*>(xc + 2048);
        const float4 v3 = *reinterpret_cast<const float4*>(xc + 3072);
        const float w = sw[c];
        a0.x = fmaf(v0.x, w, a0.x); a0.y = fmaf(v0.y, w, a0.y);
        a0.z = fmaf(v0.z, w, a0.z); a0.w = fmaf(v0.w, w, a0.w);
        a1.x = fmaf(v1.x, w, a1.x); a1.y = fmaf(v1.y, w, a1.y);
        a1.z = fmaf(v1.z, w, a1.z); a1.w = fmaf(v1.w, w, a1.w);
        a2.x = fmaf(v2.x, w, a2.x); a2.y = fmaf(v2.y, w, a2.y);
        a2.z = fmaf(v2.z, w, a2.z); a2.w = fmaf(v2.w, w, a2.w);
        a3.x = fmaf(v3.x, w, a3.x); a3.y = fmaf(v3.y, w, a3.y);
        a3.z = fmaf(v3.z, w, a3.z); a3.w = fmaf(v3.w, w, a3.w);
        float s = ((v0.x + v0.y) + (v0.z + v0.w))
                + ((v1.x + v1.y) + (v1.z + v1.w))
                + ((v2.x + v2.y) + (v2.z + v2.w))
                + ((v3.x + v3.y) + (v3.z + v3.w));
        s = warp_sum(s);
        if (lane == 0) scs[c][warp] = s;
    }
    __syncthreads();

    // finalize channel sums: thread t<16 -> channel g*16+t, quarter q
    if (t < CPGR) {
        const float* r = scs[t];
        const float s = ((r[0] + r[1]) + (r[2] + r[3]))
                      + ((r[4] + r[5]) + (r[6] + r[7]));
        g_csum[((size_t)b * Cq + g * CPGR + t) * QS + q] = s;
    }

    // store partial dots (coalesced float4)
    float* pd = g_part + ((size_t)b * GRPS + g) * HWq + (size_t)q * PXQ + (size_t)t * 4;
    *reinterpret_cast<float4*>(pd)        = a0;
    *reinterpret_cast<float4*>(pd + 1024) = a1;
    *reinterpret_cast<float4*>(pd + 2048) = a2;
    *reinterpret_cast<float4*>(pd + 3072) = a3;
}

// ---------------------------------------------------------------------------
// K1b: combine 16 group partials per pixel + exact GELU -> out channel 0.
//   grid = b(16) x part(16) = 256 blocks, 256 threads, one float4 per thread.
// ---------------------------------------------------------------------------
__global__ __launch_bounds__(256) void k1b_combine(float* __restrict__ out) {
    const int p = blockIdx.x & 15;
    const int b = blockIdx.x >> 4;
    const size_t px = (size_t)p * 1024 + (size_t)threadIdx.x * 4;

    float4 s = make_float4(0.f, 0.f, 0.f, 0.f);
    #pragma unroll
    for (int g = 0; g < GRPS; ++g) {
        const float4 v = *reinterpret_cast<const float4*>(
            g_part + ((size_t)b * GRPS + g) * HWq + px);
        s.x += v.x; s.y += v.y; s.z += v.z; s.w += v.w;
    }
    float4 o;
    o.x = gelu_exact(s.x); o.y = gelu_exact(s.y);
    o.z = gelu_exact(s.z); o.w = gelu_exact(s.w);
    *reinterpret_cast<float4*>(out + (size_t)b * 4 * HWq + px) = o;
}

// ---------------------------------------------------------------------------
// K2: one block per batch sample (16 blocks x 256 threads).
// ---------------------------------------------------------------------------
__device__ __forceinline__ void proj_cols(const float* __restrict__ W,
                                          const float* __restrict__ bias,
                                          const float* sp, float* dst,
                                          int warp, int lane) {
    #pragma unroll 2
    for (int i = 0; i < 16; ++i) {
        const int col = warp * 16 + i;
        float a = 0.f;
        #pragma unroll
        for (int k = 0; k < 8; ++k) {
            const int idx = k * 32 + lane;
            a = fmaf(__ldg(W + col * Cq + idx), sp[idx], a);
        }
        a = warp_sum(a);
        if (lane == 0) dst[col] = a + bias[col];
    }
}

__global__ __launch_bounds__(256) void k2_perbatch(
    const float* __restrict__ Wg, const float* __restrict__ bg,
    const float* __restrict__ Wt, const float* __restrict__ bt,
    const float* __restrict__ Wp, const float* __restrict__ bp,
    const float* __restrict__ Wf, const float* __restrict__ bf,
    const float* __restrict__ Wz, const float* __restrict__ bz)
{
    __shared__ float sp[Cq];
    __shared__ float s_g[INTERq], s_th[INTERq], s_ph[INTERq];
    __shared__ float sf_sh;

    const int b    = blockIdx.x;
    const int t    = threadIdx.x;
    const int lane = t & 31;
    const int warp = t >> 5;

    {
        const float4 cs = *reinterpret_cast<const float4*>(
            g_csum + ((size_t)b * Cq + t) * QS);
        const float p = ((cs.x + cs.y) + (cs.z + cs.w)) * (1.0f / (float)HWq);
        sp[t] = p;
        g_p[b * Cq + t] = p;
    }
    __syncthreads();

    proj_cols(Wg, bg, sp, s_g,  warp, lane);
    proj_cols(Wt, bt, sp, s_th, warp, lane);
    proj_cols(Wp, bp, sp, s_ph, warp, lane);
    __syncthreads();

    if (warp == 0) {
        float a = 0.f;
        #pragma unroll
        for (int k = 0; k < 8; ++k) {
            const int i = k * 32 + lane;
            const float v = (i < INTERq) ? s_th[i] : s_ph[i - INTERq];
            a = fmaf(v, __ldg(Wf + i), a);
        }
        a = warp_sum(a);
        if (lane == 0) sf_sh = fmaxf(a + bf[0], 0.f);
    }
    __syncthreads();
    const float f = sf_sh;

    #pragma unroll 2
    for (int i = 0; i < 32; ++i) {
        const int col = warp * 32 + i;
        float a = 0.f;
        #pragma unroll
        for (int k = 0; k < 4; ++k) {
            const int idx = k * 32 + lane;
            a = fmaf(__ldg(Wz + col * INTERq + idx), s_g[idx], a);
        }
        a = warp_sum(a);
        if (lane == 0) g_wy[b * Cq + col] = fmaf(f, a, bz[col]);
    }
}

// ---------------------------------------------------------------------------
// K3: single block, 512 threads. BN over batch + residual, warp-per-sample
//     top-3 via shuffle-argmax (ties -> lowest index, matches lax.top_k).
// ---------------------------------------------------------------------------
__global__ __launch_bounds__(512) void k3_bn_topk(const float* __restrict__ gamma,
                                                  const float* __restrict__ beta) {
    __shared__ float sz[Bq * Cq];
    const int t = threadIdx.x;

    if (t < Cq) {
        const int c = t;
        float vals[Bq];
        #pragma unroll
        for (int b = 0; b < Bq; ++b) vals[b] = g_wy[b * Cq + c];
        float m = 0.f;
        #pragma unroll
        for (int b = 0; b < Bq; ++b) m += vals[b];
        m *= (1.0f / (float)Bq);
        float var = 0.f;
        #pragma unroll
        for (int b = 0; b < Bq; ++b) { const float d = vals[b] - m; var = fmaf(d, d, var); }
        var *= (1.0f / (float)Bq);
        const float inv = rsqrtf(var + 1e-5f);
        const float ga = gamma[c], be = beta[c];
        #pragma unroll
        for (int b = 0; b < Bq; ++b)
            sz[b * Cq + c] = fmaf(ga * (vals[b] - m), inv, be) + g_p[b * Cq + c];
    }
    __syncthreads();

    const int warp = t >> 5;   // 16 warps = 16 samples
    const int lane = t & 31;
    {
        float v[8];
        const int base = warp * Cq;
        #pragma unroll
        for (int k = 0; k < 8; ++k) v[k] = sz[base + k * 32 + lane];

        for (int j = 0; j < 3; ++j) {
            float bv = -INFINITY;
            int   bi = 0x7fffffff;
            #pragma unroll
            for (int k = 0; k < 8; ++k) {
                const int idx = k * 32 + lane;
                if (v[k] > bv) { bv = v[k]; bi = idx; }
            }
            #pragma unroll
            for (int off = 16; off > 0; off >>= 1) {
                const float ov = __shfl_down_sync(0xffffffffu, bv, off);
                const int   oi = __shfl_down_sync(0xffffffffu, bi, off);
                if (ov > bv || (ov == bv && oi < bi)) { bv = ov; bi = oi; }
            }
            bi = __shfl_sync(0xffffffffu, bi, 0);
            if (lane == 0) g_idx[warp * 3 + j] = bi;
            const int kk = bi >> 5;
            if ((bi & 31) == lane) {
                #pragma unroll
                for (int k = 0; k < 8; ++k) if (k == kk) v[k] = -INFINITY;
            }
        }
    }
}

// ---------------------------------------------------------------------------
// K4: gather top-3 channels into output channels 1..3.
// ---------------------------------------------------------------------------
__global__ __launch_bounds__(256) void k4_gather(const float* __restrict__ x,
                                                 float* __restrict__ out) {
    const int q    = blockIdx.x >> 4;   // b*3 + j
    const int part = blockIdx.x & 15;
    const int b = q / 3, j = q % 3;
    const int ch = g_idx[b * 3 + j];
    const size_t pos = (size_t)part * 1024 + (size_t)threadIdx.x * 4;
    const float4 v = *reinterpret_cast<const float4*>(
        x + ((size_t)b * Cq + ch) * HWq + pos);
    *reinterpret_cast<float4*>(
        out + ((size_t)b * 4 + 1 + j) * HWq + pos) = v;
}

extern "C" void kernel_launch(void* const* d_in, const int* in_sizes, int n_in,
                              void* d_out, int out_size) {
    const float* x     = (const float*)d_in[0];
    const float* Wg    = (const float*)d_in[1];
    const float* bg    = (const float*)d_in[2];
    const float* Wt    = (const float*)d_in[3];
    const float* bt    = (const float*)d_in[4];
    const float* Wp    = (const float*)d_in[5];
    const float* bp    = (const float*)d_in[6];
    const float* Wf    = (const float*)d_in[7];
    const float* bf    = (const float*)d_in[8];
    const float* Wz    = (const float*)d_in[9];
    const float* bz    = (const float*)d_in[10];
    const float* gamma = (const float*)d_in[11];
    const float* beta  = (const float*)d_in[12];
    const float* W3    = (const float*)d_in[13];
    float* out = (float*)d_out;

    k1a_stream<<<Bq * GRPS * QS, 256>>>(x, W3);
    k1b_combine<<<Bq * 16, 256>>>(out);
    k2_perbatch<<<Bq, 256>>>(Wg, bg, Wt, bt, Wp, bp, Wf, bf, Wz, bz);
    k3_bn_topk<<<1, 512>>>(gamma, beta);
    k4_gather<<<Bq * 3 * 16, 256>>>(x, out);
}